// round 2
// baseline (speedup 1.0000x reference)
#include <cuda_runtime.h>
#include <cuda_bf16.h>
#include <cstdint>

// Problem: B=8, H=128, W=128, C=64, stride 2x2 max-unpool scatter-add.
// inputs  : [8,128,128,64] float32  -> 8,388,608 elements
// indices : [8,128,128,64] int (32 or 64!) -> per-batch flat index into 256*256*64
// output  : [8,256,256,64] float32  -> 33,554,432 elements
static constexpr long long PER_BATCH_IN  = 128LL * 128 * 64;      // 2^20
static constexpr long long PER_BATCH_OUT = 256LL * 256 * 64;      // 2^22
static constexpr long long TOTAL_IN      = 8 * PER_BATCH_IN;      // 8,388,608
static constexpr long long TOTAL_OUT     = 8 * PER_BATCH_OUT;     // 33,554,432

// Runtime-detected layout flags (set by probe_kernel, read by scatter kernel).
__device__ int g_swap;   // 1 if d_in[0] is the indices buffer
__device__ int g_is64;   // 1 if indices are int64

// ---------------------------------------------------------------------------
// Probe: decide which buffer holds indices, and whether they are int64.
// Indices are small non-negative ints (< 2^22). Standard-normal float bit
// patterns viewed as int32 are ~1e9 or negative, so a 256-word vote is
// unambiguous. int64 values < 2^22 have all odd 32-bit words == 0.
// Deterministic: same inputs -> same flags.
// ---------------------------------------------------------------------------
__global__ void probe_kernel(const int* __restrict__ a, const int* __restrict__ b) {
    if (threadIdx.x != 0 || blockIdx.x != 0) return;
    int pa = 0, pb = 0;
    #pragma unroll 4
    for (int k = 0; k < 256; k++) {
        int va = a[k], vb = b[k];
        if (va >= 0 && va < (int)PER_BATCH_OUT) pa++;
        if (vb >= 0 && vb < (int)PER_BATCH_OUT) pb++;
    }
    int swap = (pa > pb) ? 1 : 0;
    const int* idx = swap ? a : b;
    int odd_zero = 1;
    for (int k = 0; k < 256; k++) {
        if (idx[2 * k + 1] != 0) { odd_zero = 0; break; }
    }
    g_swap = swap;
    g_is64 = odd_zero;
}

// ---------------------------------------------------------------------------
// Zero the output (harness poisons d_out with 0xAA). float4 grid-stride.
// ---------------------------------------------------------------------------
__global__ void zero_out_kernel(float4* __restrict__ out, long long n4) {
    long long i = (long long)blockIdx.x * blockDim.x + threadIdx.x;
    long long stride = (long long)gridDim.x * blockDim.x;
    const float4 z = make_float4(0.f, 0.f, 0.f, 0.f);
    for (; i < n4; i += stride) out[i] = z;
}

// ---------------------------------------------------------------------------
// Scatter-add: 4 elements per thread. float4 value load; indices via either
// one int4 (16B) or two longlong2 (2x16B). Bounds-guarded atomicAdd (REDG).
// PER_BATCH_IN % 4 == 0, so all 4 elements share the batch.
// ---------------------------------------------------------------------------
__global__ void unpool_scatter_kernel(const void* __restrict__ p0,
                                      const void* __restrict__ p1,
                                      float*      __restrict__ out) {
    const int swap = g_swap;
    const int is64 = g_is64;
    const float* in  = (const float*)(swap ? p1 : p0);
    const void*  idx = swap ? p0 : p1;

    long long t = (long long)blockIdx.x * blockDim.x + threadIdx.x;
    long long i = t << 2;  // 4 elements per thread
    if (i >= TOTAL_IN) return;

    const float4 v = *reinterpret_cast<const float4*>(in + i);

    long long j0, j1, j2, j3;
    if (is64) {
        const longlong2 a = reinterpret_cast<const longlong2*>(idx)[t * 2 + 0];
        const longlong2 b = reinterpret_cast<const longlong2*>(idx)[t * 2 + 1];
        j0 = a.x; j1 = a.y; j2 = b.x; j3 = b.y;
    } else {
        const int4 a = reinterpret_cast<const int4*>(idx)[t];
        j0 = a.x; j1 = a.y; j2 = a.z; j3 = a.w;
    }

    long long batch = i >> 20;                 // / PER_BATCH_IN
    float* ob = out + (batch << 22);           // * PER_BATCH_OUT

    if ((unsigned long long)j0 < (unsigned long long)PER_BATCH_OUT) atomicAdd(ob + j0, v.x);
    if ((unsigned long long)j1 < (unsigned long long)PER_BATCH_OUT) atomicAdd(ob + j1, v.y);
    if ((unsigned long long)j2 < (unsigned long long)PER_BATCH_OUT) atomicAdd(ob + j2, v.z);
    if ((unsigned long long)j3 < (unsigned long long)PER_BATCH_OUT) atomicAdd(ob + j3, v.w);
}

extern "C" void kernel_launch(void* const* d_in, const int* in_sizes, int n_in,
                              void* d_out, int out_size) {
    const void* p0 = d_in[0];
    const void* p1 = d_in[1];
    float* out = (float*)d_out;

    probe_kernel<<<1, 32>>>((const int*)p0, (const int*)p1);

    // Zero pass: 33,554,432 floats = 8,388,608 float4
    {
        long long n4 = TOTAL_OUT / 4;
        int block = 256;
        int grid = (int)((n4 + block - 1) / block);
        if (grid > 148 * 32) grid = 148 * 32;
        zero_out_kernel<<<grid, block>>>((float4*)out, n4);
    }

    // Scatter pass: 8,388,608 / 4 per thread = 2,097,152 threads
    {
        long long nthreads = TOTAL_IN / 4;
        int block = 256;
        int grid = (int)((nthreads + block - 1) / block);
        unpool_scatter_kernel<<<grid, block>>>(p0, p1, out);
    }
}

// round 3
// speedup vs baseline: 1.2793x; 1.2793x over previous
#include <cuda_runtime.h>
#include <cuda_bf16.h>
#include <cstdint>

// Problem: B=8, H=128, W=128, C=64, stride 2x2 max-unpool scatter-add.
// inputs  : [8,128,128,64] float32  -> 8,388,608 elements
// indices : [8,128,128,64] int32/int64 -> per-batch flat index into 256*256*64
// output  : [8,256,256,64] float32  -> 33,554,432 elements
static constexpr long long PER_BATCH_IN  = 128LL * 128 * 64;      // 2^20
static constexpr long long PER_BATCH_OUT = 256LL * 256 * 64;      // 2^22
static constexpr int NUM_BATCH = 8;

// Stage geometry: per stage, blocks [0,ZBLK) zero batch `stage`,
// blocks [ZBLK, ZBLK+SBLK) scatter batch `stage-1`.
static constexpr int BLOCK = 256;
static constexpr int ZBLK  = 1024;   // zero: 1,048,576 float4 / (1024*256) = 4 float4/thread
static constexpr int SBLK  = 1024;   // scatter: 1,048,576 elems / (1024*256) = 4 elems/thread
static constexpr int GRID  = ZBLK + SBLK;

// Runtime-detected layout flags (set by probe_kernel).
__device__ int g_swap;   // 1 if d_in[0] is the indices buffer
__device__ int g_is64;   // 1 if indices are int64

// ---------------------------------------------------------------------------
// Probe (parallel): decide which buffer holds indices and their width.
// Indices are small non-negative ints (< 2^22); standard-normal float bit
// patterns viewed as int32 are ~1e9 or negative. int64 values < 2^22 have
// every odd 32-bit word == 0.
// ---------------------------------------------------------------------------
__global__ void probe_kernel(const int* __restrict__ a, const int* __restrict__ b) {
    int k = threadIdx.x;                 // 0..255
    int va = a[k], vb = b[k];
    bool ok_a = (va >= 0 && va < (int)PER_BATCH_OUT);
    bool ok_b = (vb >= 0 && vb < (int)PER_BATCH_OUT);
    int ca = __syncthreads_count(ok_a);
    int cb = __syncthreads_count(ok_b);
    int swap = (ca > cb) ? 1 : 0;
    const int* idx = swap ? a : b;
    bool odd_nz = (idx[2 * k + 1] != 0);
    int nz = __syncthreads_count(odd_nz);
    if (k == 0) {
        g_swap = swap;
        g_is64 = (nz == 0) ? 1 : 0;
    }
}

// ---------------------------------------------------------------------------
// Stage kernel: zero batch `stage` + scatter batch `stage-1`.
// Keeping zero(b) immediately before scatter(b) (next stage) makes the 16MB
// per-batch atomic RMW working set L2-resident: atomics hit the dirty zero
// lines in L2 instead of doing DRAM read-modify-write.
// ---------------------------------------------------------------------------
__global__ void __launch_bounds__(BLOCK) stage_kernel(
        const void* __restrict__ p0,
        const void* __restrict__ p1,
        float*      __restrict__ out,
        int stage) {

    if (blockIdx.x < ZBLK) {
        // ---- zero part: batch = stage (skip on last stage) ----
        if (stage >= NUM_BATCH) return;
        float4* ob4 = reinterpret_cast<float4*>(out + ((long long)stage << 22));
        const float4 z = make_float4(0.f, 0.f, 0.f, 0.f);
        long long t = (long long)blockIdx.x * BLOCK + threadIdx.x;  // [0, 262144)
        const long long stride = (long long)ZBLK * BLOCK;
        #pragma unroll
        for (int r = 0; r < 4; r++)
            ob4[t + r * stride] = z;
    } else {
        // ---- scatter part: batch = stage - 1 (skip on first stage) ----
        if (stage == 0) return;
        const int swap = g_swap;
        const int is64 = g_is64;
        const float* in  = (const float*)(swap ? p1 : p0);
        const void*  idx = swap ? p0 : p1;

        const int b = stage - 1;
        long long t = (long long)(blockIdx.x - ZBLK) * BLOCK + threadIdx.x; // [0, 262144)
        long long tg = (long long)b * (PER_BATCH_IN / 4) + t;   // global 4-elem group id
        long long i  = tg << 2;                                  // element index

        const float4 v = *reinterpret_cast<const float4*>(in + i);

        long long j0, j1, j2, j3;
        if (is64) {
            const longlong2 a0 = reinterpret_cast<const longlong2*>(idx)[tg * 2 + 0];
            const longlong2 a1 = reinterpret_cast<const longlong2*>(idx)[tg * 2 + 1];
            j0 = a0.x; j1 = a0.y; j2 = a1.x; j3 = a1.y;
        } else {
            const int4 a = reinterpret_cast<const int4*>(idx)[tg];
            j0 = a.x; j1 = a.y; j2 = a.z; j3 = a.w;
        }

        float* ob = out + ((long long)b << 22);
        if ((unsigned long long)j0 < (unsigned long long)PER_BATCH_OUT) atomicAdd(ob + j0, v.x);
        if ((unsigned long long)j1 < (unsigned long long)PER_BATCH_OUT) atomicAdd(ob + j1, v.y);
        if ((unsigned long long)j2 < (unsigned long long)PER_BATCH_OUT) atomicAdd(ob + j2, v.z);
        if ((unsigned long long)j3 < (unsigned long long)PER_BATCH_OUT) atomicAdd(ob + j3, v.w);
    }
}

extern "C" void kernel_launch(void* const* d_in, const int* in_sizes, int n_in,
                              void* d_out, int out_size) {
    const void* p0 = d_in[0];
    const void* p1 = d_in[1];
    float* out = (float*)d_out;

    probe_kernel<<<1, 256>>>((const int*)p0, (const int*)p1);

    // Stages 0..8: stage k zeroes batch k and scatters batch k-1.
    for (int stage = 0; stage <= NUM_BATCH; stage++) {
        stage_kernel<<<GRID, BLOCK>>>(p0, p1, out, stage);
    }
}